// round 1
// baseline (speedup 1.0000x reference)
#include <cuda_runtime.h>
#include <math.h>

#define BATCH 8192
#define NFEAT 32
#define EDIM  64
#define VOCAB 1000
#define NPAIR 496
#define DIN   2544   // 32*64 + 496
#define DH1   1024
#define DH2   512
#define DOUT  1000

// Scratch (device globals — no runtime allocation allowed)
__device__ float g_h0[(size_t)BATCH * DIN];
__device__ float g_h1[(size_t)BATCH * DH1];
__device__ float g_h2[(size_t)BATCH * DH2];

// ---------------------------------------------------------------------------
// Kernel 1: embedding gather + pairwise cross features
// one block per batch row, 256 threads
// ---------------------------------------------------------------------------
__global__ __launch_bounds__(256)
void build_features_kernel(const int* __restrict__ x,
                           const float* __restrict__ emb,
                           float* __restrict__ h0) {
    __shared__ float e[NFEAT][65];   // pad 65: consecutive-j dot reads hit distinct banks
    __shared__ int idx[NFEAT];

    const int b = blockIdx.x;
    const int t = threadIdx.x;

    if (t < NFEAT) idx[t] = x[b * NFEAT + t];
    __syncthreads();

    float* __restrict__ h0row = h0 + (size_t)b * DIN;

    // Gather: 2048 elements, fully coalesced (consecutive threads -> consecutive d)
    #pragma unroll
    for (int i = t; i < NFEAT * EDIM; i += 256) {
        const int f = i >> 6;
        const int d = i & 63;
        const float v = emb[(f * VOCAB + idx[f]) * EDIM + d];
        e[f][d] = v;
        h0row[i] = v;
    }
    __syncthreads();

    // Cross features: upper-triangle (i<j) dot products, row-major pair order
    for (int p = t; p < NPAIR; p += 256) {
        int i = 0, s = 0;
        while (p >= s + (NFEAT - 1 - i)) { s += NFEAT - 1 - i; i++; }
        const int j = i + 1 + (p - s);

        float sum = 0.f;
        #pragma unroll
        for (int d = 0; d < EDIM; d += 4) {
            sum += e[i][d + 0] * e[j][d + 0];
            sum += e[i][d + 1] * e[j][d + 1];
            sum += e[i][d + 2] * e[j][d + 2];
            sum += e[i][d + 3] * e[j][d + 3];
        }
        h0row[NFEAT * EDIM + p] = sum;
    }
}

// ---------------------------------------------------------------------------
// Kernel 2: tiled SGEMM  C = act(A[M,K] @ W[K,N] + bias)
// 128x128 tile, BK=8, 8x8 per thread, 256 threads
// ACT: 0 = none, 1 = relu, 2 = sigmoid
// Requires: M % 128 == 0, K % 8 == 0, N % 4 == 0 (N need not be tile-multiple)
// ---------------------------------------------------------------------------
template<int ACT>
__global__ __launch_bounds__(256, 2)
void gemm_kernel(const float* __restrict__ A, const float* __restrict__ W,
                 const float* __restrict__ bias, float* __restrict__ C,
                 int M, int N, int K) {
    __shared__ float As[8][128];   // transposed A tile
    __shared__ float Bs[8][128];

    const int tid  = threadIdx.x;
    const int row0 = blockIdx.y * 128;
    const int col0 = blockIdx.x * 128;

    // A-tile load map: 128 rows x 8 cols, one float4 per thread
    const int arow = tid >> 1;
    const int acol = (tid & 1) << 2;
    // B-tile load map: 8 rows x 128 cols, one float4 per thread
    const int brow = tid >> 5;
    const int bcol = (tid & 31) << 2;
    // compute map: 16x16 thread grid, 8x8 micro-tile
    const int tx = (tid & 15) << 3;
    const int ty = (tid >> 4) << 3;

    float acc[8][8] = {};

    const float* aptr = A + (size_t)(row0 + arow) * K + acol;

    for (int k0 = 0; k0 < K; k0 += 8) {
        const float4 av = *(const float4*)(aptr + k0);
        As[acol + 0][arow] = av.x;
        As[acol + 1][arow] = av.y;
        As[acol + 2][arow] = av.z;
        As[acol + 3][arow] = av.w;

        float4 bv = make_float4(0.f, 0.f, 0.f, 0.f);
        if (col0 + bcol + 4 <= N)
            bv = *(const float4*)(W + (size_t)(k0 + brow) * N + col0 + bcol);
        *(float4*)&Bs[brow][bcol] = bv;

        __syncthreads();

        #pragma unroll
        for (int k = 0; k < 8; k++) {
            float ar[8], br[8];
            *(float4*)(ar + 0) = *(const float4*)&As[k][ty + 0];
            *(float4*)(ar + 4) = *(const float4*)&As[k][ty + 4];
            *(float4*)(br + 0) = *(const float4*)&Bs[k][tx + 0];
            *(float4*)(br + 4) = *(const float4*)&Bs[k][tx + 4];
            #pragma unroll
            for (int i = 0; i < 8; i++)
                #pragma unroll
                for (int j = 0; j < 8; j++)
                    acc[i][j] += ar[i] * br[j];
        }
        __syncthreads();
    }

    // Epilogue: bias + activation + store (float4, N % 4 == 0 so no straddle)
    float bb[8];
    #pragma unroll
    for (int j = 0; j < 8; j++) {
        const int c = col0 + tx + j;
        bb[j] = (c < N) ? bias[c] : 0.f;
    }

    #pragma unroll
    for (int i = 0; i < 8; i++) {
        const int r = row0 + ty + i;
        #pragma unroll
        for (int j = 0; j < 8; j += 4) {
            const int c = col0 + tx + j;
            if (c + 4 <= N) {
                float4 v;
                float* vp = (float*)&v;
                #pragma unroll
                for (int q = 0; q < 4; q++) {
                    float val = acc[i][j + q] + bb[j + q];
                    if (ACT == 1)      val = fmaxf(val, 0.f);
                    else if (ACT == 2) val = 1.f / (1.f + __expf(-val));
                    vp[q] = val;
                }
                *(float4*)(C + (size_t)r * N + c) = v;
            }
        }
    }
}

// ---------------------------------------------------------------------------
extern "C" void kernel_launch(void* const* d_in, const int* in_sizes, int n_in,
                              void* d_out, int out_size) {
    const int*   x   = (const int*)  d_in[0];
    const float* emb = (const float*)d_in[1];
    const float* W1  = (const float*)d_in[2];
    const float* b1  = (const float*)d_in[3];
    const float* W2  = (const float*)d_in[4];
    const float* b2  = (const float*)d_in[5];
    const float* W3  = (const float*)d_in[6];
    const float* b3  = (const float*)d_in[7];
    float* out = (float*)d_out;

    float *h0, *h1, *h2;
    cudaGetSymbolAddress((void**)&h0, g_h0);
    cudaGetSymbolAddress((void**)&h1, g_h1);
    cudaGetSymbolAddress((void**)&h2, g_h2);

    build_features_kernel<<<BATCH, 256>>>(x, emb, h0);

    {   // h1 = relu(h0 @ W1 + b1)   [8192,2544]x[2544,1024]
        dim3 grid(DH1 / 128, BATCH / 128);
        gemm_kernel<1><<<grid, 256>>>(h0, W1, b1, h1, BATCH, DH1, DIN);
    }
    {   // h2 = relu(h1 @ W2 + b2)   [8192,1024]x[1024,512]
        dim3 grid(DH2 / 128, BATCH / 128);
        gemm_kernel<1><<<grid, 256>>>(h1, W2, b2, h2, BATCH, DH2, DH1);
    }
    {   // out = sigmoid(h2 @ W3 + b3)  [8192,512]x[512,1000]
        dim3 grid((DOUT + 127) / 128, BATCH / 128);
        gemm_kernel<2><<<grid, 256>>>(h2, W3, b3, out, BATCH, DOUT, DH2);
    }
}

// round 2
// speedup vs baseline: 2.3533x; 2.3533x over previous
#include <cuda_runtime.h>
#include <cuda_bf16.h>
#include <math.h>

#define BATCH 8192
#define NFEAT 32
#define EDIM  64
#define VOCAB 1000
#define NPAIR 496
#define DIN   2544
#define K1P   2560      // DIN padded to multiple of 32
#define DH1   1024
#define DH2   512
#define DOUT  1000
#define N3P   1024      // DOUT padded to multiple of 64

typedef __nv_bfloat16 bf16;

// ---------------- scratch (device globals; no runtime allocation) ----------
__device__ bf16 g_h0hi[(size_t)BATCH * K1P];
__device__ bf16 g_h0lo[(size_t)BATCH * K1P];
__device__ bf16 g_h1hi[(size_t)BATCH * DH1];
__device__ bf16 g_h1lo[(size_t)BATCH * DH1];
__device__ bf16 g_h2hi[(size_t)BATCH * DH2];
__device__ bf16 g_h2lo[(size_t)BATCH * DH2];
__device__ bf16 g_W1hi[(size_t)DH1 * K1P];
__device__ bf16 g_W1lo[(size_t)DH1 * K1P];
__device__ bf16 g_W2hi[(size_t)DH2 * DH1];
__device__ bf16 g_W2lo[(size_t)DH2 * DH1];
__device__ bf16 g_W3hi[(size_t)N3P * DH2];
__device__ bf16 g_W3lo[(size_t)N3P * DH2];

// ---------------- small helpers -------------------------------------------
__device__ __forceinline__ unsigned smem_u32(const void* p) {
    return (unsigned)__cvta_generic_to_shared(p);
}
__device__ __forceinline__ void cp_async16(unsigned dst, const void* src) {
    asm volatile("cp.async.cg.shared.global [%0], [%1], 16;\n" :: "r"(dst), "l"(src));
}
__device__ __forceinline__ void cp_commit() { asm volatile("cp.async.commit_group;\n"); }
__device__ __forceinline__ void cp_wait1()  { asm volatile("cp.async.wait_group 1;\n"); }

__device__ __forceinline__ void ldsm4(unsigned addr, unsigned& r0, unsigned& r1,
                                      unsigned& r2, unsigned& r3) {
    asm volatile("ldmatrix.sync.aligned.m8n8.x4.shared.b16 {%0,%1,%2,%3}, [%4];\n"
                 : "=r"(r0), "=r"(r1), "=r"(r2), "=r"(r3) : "r"(addr));
}
__device__ __forceinline__ void mma_bf16(float c[4], const unsigned a[4],
                                         unsigned b0, unsigned b1) {
    asm volatile("mma.sync.aligned.m16n8k16.row.col.f32.bf16.bf16.f32 "
                 "{%0,%1,%2,%3},{%4,%5,%6,%7},{%8,%9},{%0,%1,%2,%3};\n"
                 : "+f"(c[0]), "+f"(c[1]), "+f"(c[2]), "+f"(c[3])
                 : "r"(a[0]), "r"(a[1]), "r"(a[2]), "r"(a[3]), "r"(b0), "r"(b1));
}
__device__ __forceinline__ void split_bf16(float v, bf16& h, bf16& l) {
    h = __float2bfloat16(v);
    l = __float2bfloat16(v - __bfloat162float(h));
}

// ---------------------------------------------------------------------------
// Weight conversion: W[K][N] fp32 -> transposed hi/lo bf16 [Npad][Kpad], zero pad
// block (32,8), grid (ceil(Npad/32), ceil(Kpad/32))
// ---------------------------------------------------------------------------
__global__ void convert_w_kernel(const float* __restrict__ W,
                                 bf16* __restrict__ hi, bf16* __restrict__ lo,
                                 int K, int N, int Kpad, int Npad) {
    __shared__ float t[32][33];
    const int n0 = blockIdx.x * 32;
    const int k0 = blockIdx.y * 32;
    for (int r = threadIdx.y; r < 32; r += 8) {
        int k = k0 + r, n = n0 + threadIdx.x;
        t[r][threadIdx.x] = (k < K && n < N) ? W[(size_t)k * N + n] : 0.f;
    }
    __syncthreads();
    for (int r = threadIdx.y; r < 32; r += 8) {
        int n = n0 + r, k = k0 + threadIdx.x;
        if (n < Npad && k < Kpad) {
            float v = t[threadIdx.x][r];
            bf16 h, l; split_bf16(v, h, l);
            hi[(size_t)n * Kpad + k] = h;
            lo[(size_t)n * Kpad + k] = l;
        }
    }
}

// ---------------------------------------------------------------------------
// Feature build: gather + pairwise dots, emitted as bf16 hi/lo (padded to K1P)
// ---------------------------------------------------------------------------
__global__ __launch_bounds__(256)
void build_features_kernel(const int* __restrict__ x,
                           const float* __restrict__ emb,
                           bf16* __restrict__ hhi, bf16* __restrict__ hlo) {
    __shared__ float e[NFEAT][65];
    __shared__ int idx[NFEAT];
    const int b = blockIdx.x;
    const int t = threadIdx.x;
    if (t < NFEAT) idx[t] = x[b * NFEAT + t];
    __syncthreads();

    const size_t base = (size_t)b * K1P;
    #pragma unroll
    for (int i = t; i < NFEAT * EDIM; i += 256) {
        const int f = i >> 6, d = i & 63;
        const float v = emb[(f * VOCAB + idx[f]) * EDIM + d];
        e[f][d] = v;
        bf16 h, l; split_bf16(v, h, l);
        hhi[base + i] = h;
        hlo[base + i] = l;
    }
    __syncthreads();

    for (int p = t; p < NPAIR; p += 256) {
        int i = 0, s = 0;
        while (p >= s + (NFEAT - 1 - i)) { s += NFEAT - 1 - i; i++; }
        const int j = i + 1 + (p - s);
        float sum = 0.f;
        #pragma unroll
        for (int d = 0; d < EDIM; d += 4) {
            sum += e[i][d + 0] * e[j][d + 0];
            sum += e[i][d + 1] * e[j][d + 1];
            sum += e[i][d + 2] * e[j][d + 2];
            sum += e[i][d + 3] * e[j][d + 3];
        }
        bf16 h, l; split_bf16(sum, h, l);
        hhi[base + NFEAT * EDIM + p] = h;
        hlo[base + NFEAT * EDIM + p] = l;
    }
    if (t < K1P - DIN) {
        hhi[base + DIN + t] = __float2bfloat16(0.f);
        hlo[base + DIN + t] = __float2bfloat16(0.f);
    }
}

// ---------------------------------------------------------------------------
// Split-precision bf16 tensor-core GEMM:
//   C[M,N] = act( A @ B^T + bias ),  A: [M,Kp] hi/lo,  B: [Npad,Kp] hi/lo (W^T)
//   acc = Ahi*Bhi + Ahi*Blo + Alo*Bhi  (fp32 accumulate)
// BM=128, BN=64, BK=32; 256 threads, 8 warps as 4(m) x 2(n); warp tile 32x32.
// ACT==1: relu -> bf16 hi/lo outputs (Chi/Clo, stride ldc)
// ACT==2: sigmoid -> fp32 output Cf (stride N, cols guarded)
// ---------------------------------------------------------------------------
#define BM 128
#define BN 64
#define BK 32
#define SPAD 40                       // smem row stride (elems) = 80B: 16B-aligned, conflict-free
#define A_BYTES (BM * SPAD * 2)       // 10240
#define B_BYTES (BN * SPAD * 2)       // 5120
#define STAGE_BYTES (2 * A_BYTES + 2 * B_BYTES)   // 30720
#define SMEM_TOTAL (2 * STAGE_BYTES)              // 61440

template<int ACT>
__global__ __launch_bounds__(256)
void mma_gemm_kernel(const bf16* __restrict__ Ahi, const bf16* __restrict__ Alo,
                     const bf16* __restrict__ Bhi, const bf16* __restrict__ Blo,
                     const float* __restrict__ bias,
                     bf16* __restrict__ Chi, bf16* __restrict__ Clo,
                     float* __restrict__ Cf,
                     int M, int N, int Kp, int ldc) {
    extern __shared__ __align__(16) char smem[];

    const int tid  = threadIdx.x;
    const int lane = tid & 31;
    const int wid  = tid >> 5;
    const int wm   = (wid >> 1) * 32;   // warp m offset in block tile
    const int wn   = (wid & 1) * 32;    // warp n offset
    const int row0 = blockIdx.y * BM;
    const int col0 = blockIdx.x * BN;

    char* sA[2][2];
    char* sB[2][2];
    #pragma unroll
    for (int st = 0; st < 2; st++) {
        sA[st][0] = smem + st * STAGE_BYTES;
        sA[st][1] = sA[st][0] + A_BYTES;
        sB[st][0] = sA[st][1] + A_BYTES;
        sB[st][1] = sB[st][0] + B_BYTES;
    }

    // cp.async load maps
    const int a_r  = 0;                          // (computed inline)
    (void)a_r;

    // ldmatrix lane address components
    const int la_row = lane & 15;
    const int la_col = (lane >> 4) << 3;
    const int lb_row = (lane & 7) + ((lane >> 4) << 3);
    const int lb_col = ((lane >> 3) & 1) << 3;

    float acc[2][4][4];
    #pragma unroll
    for (int mi = 0; mi < 2; mi++)
        #pragma unroll
        for (int nb = 0; nb < 4; nb++)
            #pragma unroll
            for (int q = 0; q < 4; q++) acc[mi][nb][q] = 0.f;

    auto load_stage = [&](int st, int k0) {
        #pragma unroll
        for (int p = 0; p < 2; p++) {
            const int c = tid + p * 256;
            const int r = c >> 2, col = (c & 3) * 8;
            const size_t goff = (size_t)(row0 + r) * Kp + k0 + col;
            const unsigned soff = (unsigned)((r * SPAD + col) * 2);
            cp_async16(smem_u32(sA[st][0] + soff), Ahi + goff);
            cp_async16(smem_u32(sA[st][1] + soff), Alo + goff);
        }
        {
            const int r = tid >> 2, col = (tid & 3) * 8;
            const size_t goff = (size_t)(col0 + r) * Kp + k0 + col;
            const unsigned soff = (unsigned)((r * SPAD + col) * 2);
            cp_async16(smem_u32(sB[st][0] + soff), Bhi + goff);
            cp_async16(smem_u32(sB[st][1] + soff), Blo + goff);
        }
    };

    const int ntiles = Kp / BK;
    load_stage(0, 0);
    cp_commit();

    for (int kt = 0; kt < ntiles; kt++) {
        const int cur = kt & 1;
        const int nxt = cur ^ 1;
        if (kt + 1 < ntiles) load_stage(nxt, (kt + 1) * BK);
        cp_commit();
        cp_wait1();
        __syncthreads();

        #pragma unroll
        for (int ks = 0; ks < BK; ks += 16) {
            unsigned ah[2][4], al[2][4], bh[2][4], bl[2][4];
            #pragma unroll
            for (int mi = 0; mi < 2; mi++) {
                const unsigned off =
                    (unsigned)(((wm + mi * 16 + la_row) * SPAD + ks + la_col) * 2);
                ldsm4(smem_u32(sA[cur][0] + off), ah[mi][0], ah[mi][1], ah[mi][2], ah[mi][3]);
                ldsm4(smem_u32(sA[cur][1] + off), al[mi][0], al[mi][1], al[mi][2], al[mi][3]);
            }
            #pragma unroll
            for (int np = 0; np < 2; np++) {
                const unsigned off =
                    (unsigned)(((wn + np * 16 + lb_row) * SPAD + ks + lb_col) * 2);
                ldsm4(smem_u32(sB[cur][0] + off), bh[np][0], bh[np][1], bh[np][2], bh[np][3]);
                ldsm4(smem_u32(sB[cur][1] + off), bl[np][0], bl[np][1], bl[np][2], bl[np][3]);
            }
            #pragma unroll
            for (int mi = 0; mi < 2; mi++) {
                #pragma unroll
                for (int nb = 0; nb < 4; nb++) {
                    const unsigned b0h = bh[nb >> 1][(nb & 1) * 2];
                    const unsigned b1h = bh[nb >> 1][(nb & 1) * 2 + 1];
                    const unsigned b0l = bl[nb >> 1][(nb & 1) * 2];
                    const unsigned b1l = bl[nb >> 1][(nb & 1) * 2 + 1];
                    mma_bf16(acc[mi][nb], ah[mi], b0h, b1h);   // hi*hi
                    mma_bf16(acc[mi][nb], ah[mi], b0l, b1l);   // hi*lo
                    mma_bf16(acc[mi][nb], al[mi], b0h, b1h);   // lo*hi
                }
            }
        }
        __syncthreads();
    }

    // -------- epilogue --------
    #pragma unroll
    for (int mi = 0; mi < 2; mi++) {
        #pragma unroll
        for (int nb = 0; nb < 4; nb++) {
            const int rg = row0 + wm + mi * 16 + (lane >> 2);
            const int cg = col0 + wn + nb * 8 + (lane & 3) * 2;
            float b0 = 0.f, b1 = 0.f;
            if (ACT == 2) {
                if (cg < N)     b0 = bias[cg];
                if (cg + 1 < N) b1 = bias[cg + 1];
            } else {
                b0 = bias[cg];
                b1 = bias[cg + 1];
            }
            const float* a = acc[mi][nb];
            #pragma unroll
            for (int h = 0; h < 2; h++) {
                const int r = rg + h * 8;
                float v0 = a[h * 2 + 0] + b0;
                float v1 = a[h * 2 + 1] + b1;
                if (ACT == 1) {
                    v0 = fmaxf(v0, 0.f);
                    v1 = fmaxf(v1, 0.f);
                    bf16 h0, l0, h1, l1;
                    split_bf16(v0, h0, l0);
                    split_bf16(v1, h1, l1);
                    __nv_bfloat162 ph, pl;
                    ph.x = h0; ph.y = h1;
                    pl.x = l0; pl.y = l1;
                    *(__nv_bfloat162*)(Chi + (size_t)r * ldc + cg) = ph;
                    *(__nv_bfloat162*)(Clo + (size_t)r * ldc + cg) = pl;
                } else {
                    if (cg < N) {
                        v0 = 1.f / (1.f + __expf(-v0));
                        v1 = 1.f / (1.f + __expf(-v1));
                        float2 o; o.x = v0; o.y = v1;
                        *(float2*)(Cf + (size_t)r * N + cg) = o;
                    }
                }
            }
        }
    }
}

// ---------------------------------------------------------------------------
extern "C" void kernel_launch(void* const* d_in, const int* in_sizes, int n_in,
                              void* d_out, int out_size) {
    const int*   x   = (const int*)  d_in[0];
    const float* emb = (const float*)d_in[1];
    const float* W1  = (const float*)d_in[2];
    const float* b1  = (const float*)d_in[3];
    const float* W2  = (const float*)d_in[4];
    const float* b2  = (const float*)d_in[5];
    const float* W3  = (const float*)d_in[6];
    const float* b3  = (const float*)d_in[7];
    float* out = (float*)d_out;

    bf16 *h0hi, *h0lo, *h1hi, *h1lo, *h2hi, *h2lo;
    bf16 *w1hi, *w1lo, *w2hi, *w2lo, *w3hi, *w3lo;
    cudaGetSymbolAddress((void**)&h0hi, g_h0hi);
    cudaGetSymbolAddress((void**)&h0lo, g_h0lo);
    cudaGetSymbolAddress((void**)&h1hi, g_h1hi);
    cudaGetSymbolAddress((void**)&h1lo, g_h1lo);
    cudaGetSymbolAddress((void**)&h2hi, g_h2hi);
    cudaGetSymbolAddress((void**)&h2lo, g_h2lo);
    cudaGetSymbolAddress((void**)&w1hi, g_W1hi);
    cudaGetSymbolAddress((void**)&w1lo, g_W1lo);
    cudaGetSymbolAddress((void**)&w2hi, g_W2hi);
    cudaGetSymbolAddress((void**)&w2lo, g_W2lo);
    cudaGetSymbolAddress((void**)&w3hi, g_W3hi);
    cudaGetSymbolAddress((void**)&w3lo, g_W3lo);

    cudaFuncSetAttribute(mma_gemm_kernel<1>,
                         cudaFuncAttributeMaxDynamicSharedMemorySize, SMEM_TOTAL);
    cudaFuncSetAttribute(mma_gemm_kernel<2>,
                         cudaFuncAttributeMaxDynamicSharedMemorySize, SMEM_TOTAL);

    // weight conversion (transpose + hi/lo split + zero pad)
    {
        dim3 blk(32, 8);
        convert_w_kernel<<<dim3(DH1 / 32, K1P / 32), blk>>>(W1, w1hi, w1lo, DIN, DH1, K1P, DH1);
        convert_w_kernel<<<dim3(DH2 / 32, DH1 / 32), blk>>>(W2, w2hi, w2lo, DH1, DH2, DH1, DH2);
        convert_w_kernel<<<dim3(N3P / 32, DH2 / 32), blk>>>(W3, w3hi, w3lo, DH2, DOUT, DH2, N3P);
    }

    build_features_kernel<<<BATCH, 256>>>(x, emb, h0hi, h0lo);

    // layer 1: [8192,2560] x [1024,2560]^T -> relu -> h1 (bf16 hi/lo)
    mma_gemm_kernel<1><<<dim3(DH1 / BN, BATCH / BM), 256, SMEM_TOTAL>>>(
        h0hi, h0lo, w1hi, w1lo, b1, h1hi, h1lo, nullptr, BATCH, DH1, K1P, DH1);
    // layer 2: [8192,1024] x [512,1024]^T -> relu -> h2
    mma_gemm_kernel<1><<<dim3(DH2 / BN, BATCH / BM), 256, SMEM_TOTAL>>>(
        h1hi, h1lo, w2hi, w2lo, b2, h2hi, h2lo, nullptr, BATCH, DH2, DH1, DH2);
    // layer 3: [8192,512] x [1024,512]^T -> sigmoid -> out fp32 (cols < 1000)
    mma_gemm_kernel<2><<<dim3(N3P / BN, BATCH / BM), 256, SMEM_TOTAL>>>(
        h2hi, h2lo, w3hi, w3lo, b3, nullptr, nullptr, out, BATCH, DOUT, DH2, 0);
}